// round 6
// baseline (speedup 1.0000x reference)
#include <cuda_runtime.h>

#define BB 4
#define CC 8
#define HH 1024
#define WW 1024
#define HWIMG (HH*WW)
#define LN 65536          // 256*256 low-res pixels per image
#define YSEG 64
#define W31F ((float)(1.0/31.0))   // fl(1/31), identical to jnp ones/31 weight

// ---------------- device scratch (static: no runtime allocation) ----------------
// NOTE: every array touched via float4 is __align__(16): a bare __device__
// float[] only guarantees 4B alignment and its placement shifts with module
// layout -> intermittent 'misaligned address' traps (root cause of R4 fail).
__device__ double g_AtA[BB][45];     // upper-tri of 9x9 normal matrix
__device__ double g_Atb[BB][9];
__device__ double g_sumM[BB];
__device__ float  g_sol[BB][9];
__device__ float  g_cP[BB];
__device__ double g_lossC, g_lossA;

__device__ __align__(16) float g_M[BB*HWIMG];   // synthesized intensity from hr_ms
__device__ __align__(16) float g_G[BB*HWIMG];   // synthesized intensity from fuse_ms
__device__ __align__(16) float g_D[BB*HWIMG];   // sum_c |fuse - hr|
// vertical pass outputs:
// planes 0..4: centered sliding sums (M, P, M^2, P^2, M*P)  [unnormalized]
// planes 5,6 : exact conv-replica   (G, G^2)                [normalized by fl(1/31)]
__device__ __align__(16) float g_V[7][BB*HWIMG];

__device__ __forceinline__ float warpSum(float v) {
#pragma unroll
    for (int d = 16; d > 0; d >>= 1) v += __shfl_down_sync(0xffffffffu, v, d);
    return v;
}

__device__ __forceinline__ int refl(int i) {        // jnp 'reflect'
    return i < 0 ? -i : (i > 1023 ? 2046 - i : i);
}

// ---------------- K0: zero accumulators (graph-replay safe) ----------------
__global__ void k_zero() {
    int t = threadIdx.x;
    if (t < BB*45) ((double*)g_AtA)[t] = 0.0;
    if (t < BB*9)  ((double*)g_Atb)[t] = 0.0;
    if (t < BB)    g_sumM[t] = 0.0;
    if (t == 0) { g_lossC = 0.0; g_lossA = 0.0; }
}

// ---------------- K1: build AtA / Atb from lr_ms and 4x4-pooled pan ----------------
__global__ void k_normal_eq(const float* __restrict__ lr_ms,
                            const float* __restrict__ pan) {
    int b = blockIdx.y;
    int t = blockIdx.x * blockDim.x + threadIdx.x;   // 0..16383
    float acc[54];
#pragma unroll
    for (int k = 0; k < 54; k++) acc[k] = 0.f;

    const float* panb = pan + (size_t)b * HWIMG;
    const float* lrb  = lr_ms + (size_t)b * CC * LN;

    for (int it = 0; it < 4; it++) {
        int n = t + it * 16384;
        int i = n >> 8, j = n & 255;
        float dp = 0.f;
        const float* pr = panb + (i * 4) * WW + j * 4;
#pragma unroll
        for (int r = 0; r < 4; r++) {
            float4 v = *(const float4*)(pr + r * WW);
            dp += v.x + v.y + v.z + v.w;
        }
        dp *= (1.0f / 16.0f);

        float a[9];
        a[0] = 1.f;
#pragma unroll
        for (int c = 0; c < 8; c++) a[c + 1] = lrb[c * LN + n];

        int idx = 0;
#pragma unroll
        for (int p = 0; p < 9; p++) {
            acc[45 + p] += a[p] * dp;
#pragma unroll
            for (int q = p; q < 9; q++) acc[idx++] += a[p] * a[q];
        }
    }

    __shared__ float sred[8][54];
    int lane = threadIdx.x & 31, wrp = threadIdx.x >> 5;
#pragma unroll
    for (int k = 0; k < 54; k++) {
        float v = warpSum(acc[k]);
        if (lane == 0) sred[wrp][k] = v;
    }
    __syncthreads();
    if (threadIdx.x < 54) {
        double s = 0.0;
        for (int w = 0; w < 8; w++) s += (double)sred[w][threadIdx.x];
        if (threadIdx.x < 45) atomicAdd(&g_AtA[b][threadIdx.x], s);
        else                  atomicAdd(&g_Atb[b][threadIdx.x - 45], s);
    }
}

// ---------------- K2: 9x9 solve (fp64 Gaussian elim w/ partial pivoting) ----------------
__global__ void k_solve() {
    int b = threadIdx.x;
    if (b >= BB) return;
    double A[9][10];
    int idx = 0;
    for (int p = 0; p < 9; p++)
        for (int q = p; q < 9; q++) { A[p][q] = g_AtA[b][idx]; A[q][p] = A[p][q]; idx++; }
    for (int p = 0; p < 9; p++) A[p][9] = g_Atb[b][p];
    g_cP[b] = (float)(g_Atb[b][0] / (double)LN);   // mean of pooled pan == mean of pan

    for (int col = 0; col < 9; col++) {
        int piv = col; double best = fabs(A[col][col]);
        for (int r = col + 1; r < 9; r++) {
            double v = fabs(A[r][col]);
            if (v > best) { best = v; piv = r; }
        }
        if (piv != col)
            for (int c = col; c < 10; c++) { double tmp = A[col][c]; A[col][c] = A[piv][c]; A[piv][c] = tmp; }
        double d = A[col][col];
        for (int r = col + 1; r < 9; r++) {
            double f = A[r][col] / d;
            for (int c = col; c < 10; c++) A[r][c] -= f * A[col][c];
        }
    }
    double x[9];
    for (int r = 8; r >= 0; r--) {
        double s = A[r][9];
        for (int c = r + 1; c < 9; c++) s -= A[r][c] * x[c];
        x[r] = s / A[r][r];
    }
    for (int k = 0; k < 9; k++) g_sol[b][k] = (float)x[k];
}

// ---------------- K3: synthesize M_, G_, D; accumulate mean of M ----------------
__global__ void k_synth(const float* __restrict__ hr_ms,
                        const float* __restrict__ fuse_ms) {
    int b = blockIdx.y;
    float s[9];
#pragma unroll
    for (int k = 0; k < 9; k++) s[k] = g_sol[b][k];
    int t = blockIdx.x * 256 + threadIdx.x;
    const float* hb = hr_ms  + (size_t)b * CC * HWIMG;
    const float* fb = fuse_ms + (size_t)b * CC * HWIMG;
    float sm = 0.f;
    for (int it = 0; it < 4; it++) {
        int p = t + it * 262144;
        float aM = 0.f, aG = 0.f, D = 0.f;
#pragma unroll
        for (int c = 0; c < 8; c++) {
            float hv = hb[c * HWIMG + p];
            float fv = fb[c * HWIMG + p];
            aM = fmaf(s[c + 1], hv, aM);
            aG = fmaf(s[c + 1], fv, aG);
            D += fabsf(fv - hv);
        }
        float M = s[0] + aM;
        float G = s[0] + aG;   // matches ref: bias + einsum
        g_M[(size_t)b * HWIMG + p] = M;
        g_G[(size_t)b * HWIMG + p] = G;
        g_D[(size_t)b * HWIMG + p] = D;
        sm += M;
    }
    __shared__ float s1[8];
    int lane = threadIdx.x & 31, wrp = threadIdx.x >> 5;
    float v1 = warpSum(sm);
    if (lane == 0) s1[wrp] = v1;
    __syncthreads();
    if (threadIdx.x == 0) {
        float a = 0;
        for (int k = 0; k < 8; k++) a += s1[k];
        atomicAdd(&g_sumM[b], (double)a);
    }
}

// ---------------- K4: vertical pass ----------------
// Fast channels (M,P centered, sliding window): planes 0..4.
// Exact G replication (uncentered, per-tap fmaf with fl(1/31), ascending taps): planes 5,6.
__global__ void k_vblur(const float* __restrict__ pan) {
    int b  = blockIdx.z;
    int x  = blockIdx.x * 256 + threadIdx.x;
    int y0 = blockIdx.y * YSEG;
    float cM = (float)(g_sumM[b] / (double)HWIMG);
    float cP = g_cP[b];
    const float* Mp = g_M + (size_t)b * HWIMG;
    const float* Gp = g_G + (size_t)b * HWIMG;
    const float* Pp = pan + (size_t)b * HWIMG;

    // init sliding sums over window [y0-15, y0+15]
    float sM = 0, sP = 0, sMM = 0, sPP = 0, sMP = 0;
    for (int k = y0 - 15; k <= y0 + 15; k++) {
        int o = refl(k) * WW + x;
        float m = Mp[o] - cM, p = Pp[o] - cP;
        sM += m; sP += p; sMM += m * m; sPP += p * p; sMP += m * p;
    }
    size_t base = (size_t)b * HWIMG + x;
    for (int y = y0; y < y0 + YSEG; y++) {
        // exact G vertical conv (31 taps, ascending, fmaf with fl(1/31))
        float aG = 0.f, aGG = 0.f;
#pragma unroll
        for (int r = 0; r < 31; r++) {
            float gv = Gp[refl(y - 15 + r) * WW + x];
            aG  = fmaf(gv, W31F, aG);
            aGG = fmaf(gv * gv, W31F, aGG);
        }
        size_t o = base + (size_t)y * WW;
        g_V[0][o] = sM;  g_V[1][o] = sP;
        g_V[2][o] = sMM; g_V[3][o] = sPP; g_V[4][o] = sMP;
        g_V[5][o] = aG;  g_V[6][o] = aGG;

        if (y + 1 < y0 + YSEG) {
            int oi = refl(y + 16) * WW + x;
            float m = Mp[oi] - cM, p = Pp[oi] - cP;
            sM += m; sP += p; sMM += m * m; sPP += p * p; sMP += m * p;
            oi = refl(y - 15) * WW + x;
            m = Mp[oi] - cM; p = Pp[oi] - cP;
            sM -= m; sP -= p; sMM -= m * m; sPP -= p * p; sMP -= m * p;
        }
    }
}

// ---------------- K5: horizontal pass + all loss math ----------------
__global__ void k_hblur_loss(const float* __restrict__ pan) {
    __shared__ float pre[5][1025];
    __shared__ __align__(16) float rowG[1024];
    __shared__ __align__(16) float rowGG[1024];
    __shared__ float wsumS[5][8];
    __shared__ float r1[8], r2[8];

    int b = blockIdx.y, y = blockIdx.x;
    int t = threadIdx.x, lane = t & 31, wrp = t >> 5;
    size_t rowbase = (size_t)b * HWIMG + (size_t)y * WW;
    float cP = g_cP[b];

    // stage exact G vertical outputs into smem
    {
        float4 vg  = *(const float4*)(&g_V[5][rowbase + t * 4]);
        float4 vgg = *(const float4*)(&g_V[6][rowbase + t * 4]);
        *(float4*)(&rowG[t * 4])  = vg;
        *(float4*)(&rowGG[t * 4]) = vgg;
    }

    // prefix sums for 5 fast channels
    float l[5][4], tsum[5];
#pragma unroll
    for (int ch = 0; ch < 5; ch++) {
        float4 v = *(const float4*)(&g_V[ch][rowbase + t * 4]);
        l[ch][0] = v.x;
        l[ch][1] = l[ch][0] + v.y;
        l[ch][2] = l[ch][1] + v.z;
        l[ch][3] = l[ch][2] + v.w;
        tsum[ch] = l[ch][3];
    }
    float wscan[5];
#pragma unroll
    for (int ch = 0; ch < 5; ch++) {
        float v = tsum[ch];
#pragma unroll
        for (int d = 1; d < 32; d <<= 1) {
            float o = __shfl_up_sync(0xffffffffu, v, d);
            if (lane >= d) v += o;
        }
        wscan[ch] = v;
        if (lane == 31) wsumS[ch][wrp] = v;
    }
    __syncthreads();
#pragma unroll
    for (int ch = 0; ch < 5; ch++) {
        float off = wscan[ch] - tsum[ch];
        for (int k = 0; k < wrp; k++) off += wsumS[ch][k];
        pre[ch][t * 4 + 0] = off;
        pre[ch][t * 4 + 1] = off + l[ch][0];
        pre[ch][t * 4 + 2] = off + l[ch][1];
        pre[ch][t * 4 + 3] = off + l[ch][2];
        if (t == 255) pre[ch][1024] = off + l[ch][3];
    }
    __syncthreads();

    float4 Pv = *(const float4*)(pan + rowbase + t * 4);
    float4 Gv = *(const float4*)(&g_G[rowbase + t * 4]);
    float4 Dv = *(const float4*)(&g_D[rowbase + t * 4]);
    float Pa[4] = {Pv.x, Pv.y, Pv.z, Pv.w};
    float Ga[4] = {Gv.x, Gv.y, Gv.z, Gv.w};
    float Da[4] = {Dv.x, Dv.y, Dv.z, Dv.w};

    const float inv961 = 1.0f / 961.0f;
    float lc = 0.f, la = 0.f;
#pragma unroll
    for (int k = 0; k < 4; k++) {
        int x = t * 4 + k;
        // ---- fast channels window sums (centered M/P stats for S) ----
        float wv[5];
#pragma unroll
        for (int ch = 0; ch < 5; ch++) {
            float s = pre[ch][min(x + 16, 1024)] - pre[ch][max(x - 15, 0)];
            if (x < 15)   s += pre[ch][16 - x]  - pre[ch][1];
            if (x > 1008) s += pre[ch][1023]    - pre[ch][2031 - x];
            wv[ch] = s * inv961;
        }
        float bM = wv[0], bP = wv[1];
        float bMM = wv[2], bPP = wv[3], bMP = wv[4];
        float stdM = sqrtf(fabsf(bMM - bM * bM) + 1e-10f);
        float stdP = sqrtf(fabsf(bPP - bP * bP) + 1e-10f);
        float cov  = bMP - bM * bP;
        float r    = cov / (stdM * stdP);
        float r2v  = r * r;
        float S    = r2v * r2v;

        // ---- exact G horizontal conv (31 taps, ascending, fmaf with fl(1/31)) ----
        float meanG = 0.f, boxGG = 0.f;
#pragma unroll
        for (int rr = 0; rr < 31; rr++) {
            int xx = x - 15 + rr;
            int rx = xx < 0 ? -xx : (xx > 1023 ? 2046 - xx : xx);
            meanG = fmaf(rowG[rx],  W31F, meanG);
            boxGG = fmaf(rowGG[rx], W31F, boxGG);
        }
        float stdG = sqrtf(fabsf(boxGG - meanG * meanG) + 1e-10f);
        float gG = (Ga[k] - meanG) / stdG;
        float gP = ((Pa[k] - cP) - bP) / stdP;

        lc += S * Da[k];
        la += fabsf((gG - gP) * (2.0f - S));
    }
    float v1 = warpSum(lc), v2 = warpSum(la);
    if (lane == 0) { r1[wrp] = v1; r2[wrp] = v2; }
    __syncthreads();
    if (t == 0) {
        float a = 0, c2 = 0;
        for (int k = 0; k < 8; k++) { a += r1[k]; c2 += r2[k]; }
        atomicAdd(&g_lossC, (double)a);
        atomicAdd(&g_lossA, (double)c2);
    }
}

// ---------------- K6: final scalar ----------------
__global__ void k_final(float* out) {
    out[0] = (float)(g_lossC / (double)((size_t)BB * CC * HWIMG) +
                     g_lossA / (double)((size_t)BB * HWIMG));
}

extern "C" void kernel_launch(void* const* d_in, const int* in_sizes, int n_in,
                              void* d_out, int out_size) {
    const float* lr   = (const float*)d_in[0];  // [4,8,256,256]
    const float* pan  = (const float*)d_in[1];  // [4,1,1024,1024]
    const float* hr   = (const float*)d_in[2];  // [4,8,1024,1024]
    const float* fuse = (const float*)d_in[3];  // [4,8,1024,1024]

    k_zero<<<1, 256>>>();
    k_normal_eq<<<dim3(64, BB), 256>>>(lr, pan);
    k_solve<<<1, 32>>>();
    k_synth<<<dim3(1024, BB), 256>>>(hr, fuse);
    k_vblur<<<dim3(4, 16, BB), 256>>>(pan);
    k_hblur_loss<<<dim3(1024, BB), 256>>>(pan);
    k_final<<<1, 1>>>((float*)d_out);
}

// round 7
// speedup vs baseline: 1.5414x; 1.5414x over previous
#include <cuda_runtime.h>

#define BB 4
#define CC 8
#define HH 1024
#define WW 1024
#define HWIMG (HH*WW)
#define LN 65536          // 256*256 low-res pixels per image
#define YSEG 32
#define W31F ((float)(1.0/31.0))   // fl(1/31), identical to jnp ones/31 weight

// ---------------- device scratch (static: no runtime allocation) ----------------
__device__ double g_AtA[BB][45];     // upper-tri of 9x9 normal matrix
__device__ double g_Atb[BB][9];
__device__ double g_sumM[BB];
__device__ float  g_sol[BB][9];
__device__ float  g_cP[BB];
__device__ double g_lossC, g_lossA;

__device__ __align__(16) float g_M[BB*HWIMG];   // synthesized intensity from hr_ms
__device__ __align__(16) float g_G[BB*HWIMG];   // synthesized intensity from fuse_ms
__device__ __align__(16) float g_D[BB*HWIMG];   // sum_c |fuse - hr|
// vertical pass outputs:
// planes 0..4: centered sliding sums (M, P, M^2, P^2, M*P)  [unnormalized]
// planes 5,6 : exact conv-replica   (G, G^2)                [normalized by fl(1/31)]
__device__ __align__(16) float g_V[7][BB*HWIMG];

__device__ __forceinline__ float warpSum(float v) {
#pragma unroll
    for (int d = 16; d > 0; d >>= 1) v += __shfl_down_sync(0xffffffffu, v, d);
    return v;
}

__device__ __forceinline__ int refl(int i) {        // jnp 'reflect'
    return i < 0 ? -i : (i > 1023 ? 2046 - i : i);
}

// ---------------- K0: zero accumulators (graph-replay safe) ----------------
__global__ void k_zero() {
    int t = threadIdx.x;
    if (t < BB*45) ((double*)g_AtA)[t] = 0.0;
    if (t < BB*9)  ((double*)g_Atb)[t] = 0.0;
    if (t < BB)    g_sumM[t] = 0.0;
    if (t == 0) { g_lossC = 0.0; g_lossA = 0.0; }
}

// ---------------- K1: build AtA / Atb from lr_ms and 4x4-pooled pan ----------------
__global__ void k_normal_eq(const float* __restrict__ lr_ms,
                            const float* __restrict__ pan) {
    int b = blockIdx.y;
    int t = blockIdx.x * blockDim.x + threadIdx.x;   // 0..16383
    float acc[54];
#pragma unroll
    for (int k = 0; k < 54; k++) acc[k] = 0.f;

    const float* panb = pan + (size_t)b * HWIMG;
    const float* lrb  = lr_ms + (size_t)b * CC * LN;

    for (int it = 0; it < 4; it++) {
        int n = t + it * 16384;
        int i = n >> 8, j = n & 255;
        float dp = 0.f;
        const float* pr = panb + (i * 4) * WW + j * 4;
#pragma unroll
        for (int r = 0; r < 4; r++) {
            float4 v = *(const float4*)(pr + r * WW);
            dp += v.x + v.y + v.z + v.w;
        }
        dp *= (1.0f / 16.0f);

        float a[9];
        a[0] = 1.f;
#pragma unroll
        for (int c = 0; c < 8; c++) a[c + 1] = lrb[c * LN + n];

        int idx = 0;
#pragma unroll
        for (int p = 0; p < 9; p++) {
            acc[45 + p] += a[p] * dp;
#pragma unroll
            for (int q = p; q < 9; q++) acc[idx++] += a[p] * a[q];
        }
    }

    __shared__ float sred[8][54];
    int lane = threadIdx.x & 31, wrp = threadIdx.x >> 5;
#pragma unroll
    for (int k = 0; k < 54; k++) {
        float v = warpSum(acc[k]);
        if (lane == 0) sred[wrp][k] = v;
    }
    __syncthreads();
    if (threadIdx.x < 54) {
        double s = 0.0;
        for (int w = 0; w < 8; w++) s += (double)sred[w][threadIdx.x];
        if (threadIdx.x < 45) atomicAdd(&g_AtA[b][threadIdx.x], s);
        else                  atomicAdd(&g_Atb[b][threadIdx.x - 45], s);
    }
}

// ---------------- K2: 9x9 solve (fp64 Gaussian elim w/ partial pivoting) ----------------
__global__ void k_solve() {
    int b = threadIdx.x;
    if (b >= BB) return;
    double A[9][10];
    int idx = 0;
    for (int p = 0; p < 9; p++)
        for (int q = p; q < 9; q++) { A[p][q] = g_AtA[b][idx]; A[q][p] = A[p][q]; idx++; }
    for (int p = 0; p < 9; p++) A[p][9] = g_Atb[b][p];
    g_cP[b] = (float)(g_Atb[b][0] / (double)LN);   // mean of pooled pan == mean of pan

    for (int col = 0; col < 9; col++) {
        int piv = col; double best = fabs(A[col][col]);
        for (int r = col + 1; r < 9; r++) {
            double v = fabs(A[r][col]);
            if (v > best) { best = v; piv = r; }
        }
        if (piv != col)
            for (int c = col; c < 10; c++) { double tmp = A[col][c]; A[col][c] = A[piv][c]; A[piv][c] = tmp; }
        double d = A[col][col];
        for (int r = col + 1; r < 9; r++) {
            double f = A[r][col] / d;
            for (int c = col; c < 10; c++) A[r][c] -= f * A[col][c];
        }
    }
    double x[9];
    for (int r = 8; r >= 0; r--) {
        double s = A[r][9];
        for (int c = r + 1; c < 9; c++) s -= A[r][c] * x[c];
        x[r] = s / A[r][r];
    }
    for (int k = 0; k < 9; k++) g_sol[b][k] = (float)x[k];
}

// ---------------- K3: synthesize M_, G_, D (float4 vectorized) ----------------
__global__ void k_synth(const float* __restrict__ hr_ms,
                        const float* __restrict__ fuse_ms) {
    int b = blockIdx.y;
    float s[9];
#pragma unroll
    for (int k = 0; k < 9; k++) s[k] = g_sol[b][k];
    int g = blockIdx.x * 256 + threadIdx.x;      // 0..262143 float4-groups
    size_t p0 = (size_t)g * 4;
    const float4* hb = (const float4*)(hr_ms  + (size_t)b * CC * HWIMG);
    const float4* fb = (const float4*)(fuse_ms + (size_t)b * CC * HWIMG);

    float4 aM = make_float4(0.f, 0.f, 0.f, 0.f);
    float4 aG = make_float4(0.f, 0.f, 0.f, 0.f);
    float4 D  = make_float4(0.f, 0.f, 0.f, 0.f);
#pragma unroll
    for (int c = 0; c < 8; c++) {
        float4 hv = hb[(size_t)c * (HWIMG/4) + g];
        float4 fv = fb[(size_t)c * (HWIMG/4) + g];
        float w = s[c + 1];
        aM.x = fmaf(w, hv.x, aM.x); aM.y = fmaf(w, hv.y, aM.y);
        aM.z = fmaf(w, hv.z, aM.z); aM.w = fmaf(w, hv.w, aM.w);
        aG.x = fmaf(w, fv.x, aG.x); aG.y = fmaf(w, fv.y, aG.y);
        aG.z = fmaf(w, fv.z, aG.z); aG.w = fmaf(w, fv.w, aG.w);
        D.x += fabsf(fv.x - hv.x); D.y += fabsf(fv.y - hv.y);
        D.z += fabsf(fv.z - hv.z); D.w += fabsf(fv.w - hv.w);
    }
    float4 M = make_float4(s[0] + aM.x, s[0] + aM.y, s[0] + aM.z, s[0] + aM.w);
    float4 G = make_float4(s[0] + aG.x, s[0] + aG.y, s[0] + aG.z, s[0] + aG.w);
    size_t ob = (size_t)b * HWIMG + p0;
    *(float4*)(g_M + ob) = M;
    *(float4*)(g_G + ob) = G;
    *(float4*)(g_D + ob) = D;

    float sm = M.x + M.y + M.z + M.w;
    __shared__ float s1[8];
    int lane = threadIdx.x & 31, wrp = threadIdx.x >> 5;
    float v1 = warpSum(sm);
    if (lane == 0) s1[wrp] = v1;
    __syncthreads();
    if (threadIdx.x == 0) {
        float a = 0;
        for (int k = 0; k < 8; k++) a += s1[k];
        atomicAdd(&g_sumM[b], (double)a);
    }
}

// ---------------- K4: vertical pass ----------------
// Fast channels (M,P centered, sliding window): planes 0..4.
// Exact G replication: 4 outputs per step share a 34-row union window ->
// 8 independent fmaf chains (latency hiding), 8.5 LDG/output instead of 31.
// Per-output tap order remains ascending (bit-identical to reference model).
__global__ void k_vblur(const float* __restrict__ pan) {
    int b  = blockIdx.z;
    int x  = blockIdx.x * 256 + threadIdx.x;
    int y0 = blockIdx.y * YSEG;
    float cM = (float)(g_sumM[b] / (double)HWIMG);
    float cP = g_cP[b];
    const float* Mp = g_M + (size_t)b * HWIMG;
    const float* Gp = g_G + (size_t)b * HWIMG;
    const float* Pp = pan + (size_t)b * HWIMG;

    // init sliding sums over window [y0-15, y0+15]
    float sM = 0, sP = 0, sMM = 0, sPP = 0, sMP = 0;
    for (int k = y0 - 15; k <= y0 + 15; k++) {
        int o = refl(k) * WW + x;
        float m = Mp[o] - cM, p = Pp[o] - cP;
        sM += m; sP += p; sMM += m * m; sPP += p * p; sMP += m * p;
    }
    size_t base = (size_t)b * HWIMG + x;

    for (int yb = y0; yb < y0 + YSEG; yb += 4) {
        // exact G vertical conv for outputs yb..yb+3 over shared 34-row union
        float aG[4]  = {0.f, 0.f, 0.f, 0.f};
        float aGG[4] = {0.f, 0.f, 0.f, 0.f};
#pragma unroll
        for (int j = 0; j < 34; j++) {
            float gv  = Gp[refl(yb - 15 + j) * WW + x];
            float gv2 = gv * gv;
#pragma unroll
            for (int o = 0; o < 4; o++) {
                if (j >= o && j <= o + 30) {        // compile-time predicate
                    aG[o]  = fmaf(gv,  W31F, aG[o]);
                    aGG[o] = fmaf(gv2, W31F, aGG[o]);
                }
            }
        }
#pragma unroll
        for (int o = 0; o < 4; o++) {
            int y = yb + o;
            size_t off = base + (size_t)y * WW;
            g_V[0][off] = sM;  g_V[1][off] = sP;
            g_V[2][off] = sMM; g_V[3][off] = sPP; g_V[4][off] = sMP;
            g_V[5][off] = aG[o]; g_V[6][off] = aGG[o];

            if (y + 1 < y0 + YSEG) {
                int oi = refl(y + 16) * WW + x;
                float m = Mp[oi] - cM, p = Pp[oi] - cP;
                sM += m; sP += p; sMM += m * m; sPP += p * p; sMP += m * p;
                oi = refl(y - 15) * WW + x;
                m = Mp[oi] - cM; p = Pp[oi] - cP;
                sM -= m; sP -= p; sMM -= m * m; sPP -= p * p; sMP -= m * p;
            }
        }
    }
}

// ---------------- K5: horizontal pass + all loss math ----------------
__global__ void k_hblur_loss(const float* __restrict__ pan) {
    __shared__ float pre[5][1025];
    __shared__ __align__(16) float extG[1056];   // reflect-extended row of V[5]
    __shared__ __align__(16) float extGG[1056];  // reflect-extended row of V[6]
    __shared__ float wsumS[5][8];
    __shared__ float r1[8], r2[8];

    int b = blockIdx.y, y = blockIdx.x;
    int t = threadIdx.x, lane = t & 31, wrp = t >> 5;
    size_t rowbase = (size_t)b * HWIMG + (size_t)y * WW;
    float cP = g_cP[b];

    // build reflect-extended rows: ext[k] = V[row][refl(k-15)], k = 0..1053
    for (int k = t; k < 1054; k += 256) {
        int sx = refl(k - 15);
        extG[k]  = g_V[5][rowbase + sx];
        extGG[k] = g_V[6][rowbase + sx];
    }

    // prefix sums for 5 fast channels
    float l[5][4], tsum[5];
#pragma unroll
    for (int ch = 0; ch < 5; ch++) {
        float4 v = *(const float4*)(&g_V[ch][rowbase + t * 4]);
        l[ch][0] = v.x;
        l[ch][1] = l[ch][0] + v.y;
        l[ch][2] = l[ch][1] + v.z;
        l[ch][3] = l[ch][2] + v.w;
        tsum[ch] = l[ch][3];
    }
    float wscan[5];
#pragma unroll
    for (int ch = 0; ch < 5; ch++) {
        float v = tsum[ch];
#pragma unroll
        for (int d = 1; d < 32; d <<= 1) {
            float o = __shfl_up_sync(0xffffffffu, v, d);
            if (lane >= d) v += o;
        }
        wscan[ch] = v;
        if (lane == 31) wsumS[ch][wrp] = v;
    }
    __syncthreads();
#pragma unroll
    for (int ch = 0; ch < 5; ch++) {
        float off = wscan[ch] - tsum[ch];
        for (int k = 0; k < wrp; k++) off += wsumS[ch][k];
        pre[ch][t * 4 + 0] = off;
        pre[ch][t * 4 + 1] = off + l[ch][0];
        pre[ch][t * 4 + 2] = off + l[ch][1];
        pre[ch][t * 4 + 3] = off + l[ch][2];
        if (t == 255) pre[ch][1024] = off + l[ch][3];
    }
    __syncthreads();

    // exact G horizontal conv: 4 outputs share ext[x0 .. x0+33];
    // vectorized LDS.128 window reads, 8 independent fmaf chains.
    int x0 = t * 4;
    float mG[4]  = {0.f, 0.f, 0.f, 0.f};
    float bG2[4] = {0.f, 0.f, 0.f, 0.f};
#pragma unroll
    for (int q = 0; q < 9; q++) {
        float4 v  = *(const float4*)(&extG[x0 + 4 * q]);
        float4 v2 = *(const float4*)(&extGG[x0 + 4 * q]);
        float gv[4]  = {v.x, v.y, v.z, v.w};
        float gg[4]  = {v2.x, v2.y, v2.z, v2.w};
#pragma unroll
        for (int e = 0; e < 4; e++) {
            int j = 4 * q + e;
            if (j < 34) {
#pragma unroll
                for (int o = 0; o < 4; o++) {
                    if (j >= o && j <= o + 30) {    // compile-time predicate
                        mG[o]  = fmaf(gv[e], W31F, mG[o]);
                        bG2[o] = fmaf(gg[e], W31F, bG2[o]);
                    }
                }
            }
        }
    }

    float4 Pv = *(const float4*)(pan + rowbase + x0);
    float4 Gv = *(const float4*)(&g_G[rowbase + x0]);
    float4 Dv = *(const float4*)(&g_D[rowbase + x0]);
    float Pa[4] = {Pv.x, Pv.y, Pv.z, Pv.w};
    float Ga[4] = {Gv.x, Gv.y, Gv.z, Gv.w};
    float Da[4] = {Dv.x, Dv.y, Dv.z, Dv.w};

    const float inv961 = 1.0f / 961.0f;
    float lc = 0.f, la = 0.f;
#pragma unroll
    for (int k = 0; k < 4; k++) {
        int x = x0 + k;
        // ---- fast channels window sums (centered M/P stats for S) ----
        float wv[5];
#pragma unroll
        for (int ch = 0; ch < 5; ch++) {
            float s = pre[ch][min(x + 16, 1024)] - pre[ch][max(x - 15, 0)];
            if (x < 15)   s += pre[ch][16 - x]  - pre[ch][1];
            if (x > 1008) s += pre[ch][1023]    - pre[ch][2031 - x];
            wv[ch] = s * inv961;
        }
        float bM = wv[0], bP = wv[1];
        float bMM = wv[2], bPP = wv[3], bMP = wv[4];
        float stdM = sqrtf(fabsf(bMM - bM * bM) + 1e-10f);
        float stdP = sqrtf(fabsf(bPP - bP * bP) + 1e-10f);
        float cov  = bMP - bM * bP;
        float r    = cov / (stdM * stdP);
        float r2v  = r * r;
        float S    = r2v * r2v;

        float stdG = sqrtf(fabsf(bG2[k] - mG[k] * mG[k]) + 1e-10f);
        float gG = (Ga[k] - mG[k]) / stdG;
        float gP = ((Pa[k] - cP) - bP) / stdP;

        lc += S * Da[k];
        la += fabsf((gG - gP) * (2.0f - S));
    }
    float v1 = warpSum(lc), v2 = warpSum(la);
    if (lane == 0) { r1[wrp] = v1; r2[wrp] = v2; }
    __syncthreads();
    if (t == 0) {
        float a = 0, c2 = 0;
        for (int k = 0; k < 8; k++) { a += r1[k]; c2 += r2[k]; }
        atomicAdd(&g_lossC, (double)a);
        atomicAdd(&g_lossA, (double)c2);
    }
}

// ---------------- K6: final scalar ----------------
__global__ void k_final(float* out) {
    out[0] = (float)(g_lossC / (double)((size_t)BB * CC * HWIMG) +
                     g_lossA / (double)((size_t)BB * HWIMG));
}

extern "C" void kernel_launch(void* const* d_in, const int* in_sizes, int n_in,
                              void* d_out, int out_size) {
    const float* lr   = (const float*)d_in[0];  // [4,8,256,256]
    const float* pan  = (const float*)d_in[1];  // [4,1,1024,1024]
    const float* hr   = (const float*)d_in[2];  // [4,8,1024,1024]
    const float* fuse = (const float*)d_in[3];  // [4,8,1024,1024]

    k_zero<<<1, 256>>>();
    k_normal_eq<<<dim3(64, BB), 256>>>(lr, pan);
    k_solve<<<1, 32>>>();
    k_synth<<<dim3(1024, BB), 256>>>(hr, fuse);
    k_vblur<<<dim3(4, 32, BB), 256>>>(pan);
    k_hblur_loss<<<dim3(1024, BB), 256>>>(pan);
    k_final<<<1, 1>>>((float*)d_out);
}